// round 5
// baseline (speedup 1.0000x reference)
#include <cuda_runtime.h>
#include <cuda_bf16.h>

// Problem constants (shapes fixed by the dataset):
//   x:  (8, 64, 56, 56) fp32
//   lb: (64, 1, 1, 32) fp32   (tiled linspace left edges)
//   rb: (64, 1, 1, 32) fp32   (tiled linspace right edges)
//   out:(8, 32, 56, 56) fp32
#define NB   8
#define CI   64
#define CO   32
#define HW   3136              // 56*56
#define NPOS (NB * HW)         // 25088
#define T    64                // threads per block; NPOS % T == 0 -> 392 blocks

__global__ __launch_bounds__(T)
void local_basis_kernel(const float* __restrict__ x,
                        const float* __restrict__ lb,
                        const float* __restrict__ rb,
                        float* __restrict__ out)
{
    // Per-thread private accumulators for the 32 output bins.
    // Dynamic bin index forces them out of registers; bin-major layout
    // acc[k*T + tid] puts each lane in its own bank -> conflict-free.
    __shared__ float acc[CO * T];

    const int tid = threadIdx.x;
    const int p   = blockIdx.x * T + tid;       // linear (b, h, w) position
    const int b   = p / HW;
    const int s   = p - b * HW;

    // Bin geometry from the actual input arrays (uniform across channels/bins).
    const float lb0   = lb[0];
    const float w     = rb[0] - lb0;
    const float inv_w = 1.0f / w;
    const float norm  = 4.0f * inv_w * inv_w;   // norm_const = 4/(rb-lb)^2

    #pragma unroll
    for (int k = 0; k < CO; k++) acc[k * T + tid] = 0.0f;

    const float* xp = x + (size_t)b * CI * HW + s;

    #pragma unroll
    for (int c = 0; c < CI; c++) {
        const float xv = xp[c * HW];
        const float t  = (xv - lb0) * inv_w;    // fractional bin position
        const int   k  = (int)t;                // trunc-toward-0: negative t -> k=0,
                                                // but d1 clamp kills that case
        if (t >= 0.0f && k < CO) {
            const float kf  = (float)k;
            const float lbk = fmaf(kf, w, lb0); // exact: -1 + k/16
            const float d1r = xv - lbk;         // == left inside the bin
            const float d1  = fmaxf(d1r, 0.0f);
            const float d2  = fmaxf(w - d1r, 0.0f); // == rb_k - x inside the bin
            const float v   = d1 * d2 * norm;
            acc[k * T + tid] = fmaf(v, v, acc[k * T + tid]);
        }
        // x outside [lb0, lb0 + CO*w): every bin's left*right product is 0
        // in the reference too (left=0 or right<=0), so skipping is exact.
    }

    float* op = out + (size_t)b * CO * HW + s;
    #pragma unroll
    for (int k = 0; k < CO; k++)
        op[k * HW] = acc[k * T + tid];
}

extern "C" void kernel_launch(void* const* d_in, const int* in_sizes, int n_in,
                              void* d_out, int out_size)
{
    const float* x  = (const float*)d_in[0];
    const float* lb = (const float*)d_in[1];
    const float* rb = (const float*)d_in[2];
    float* out      = (float*)d_out;

    local_basis_kernel<<<NPOS / T, T>>>(x, lb, rb, out);
}

// round 7
// speedup vs baseline: 1.1124x; 1.1124x over previous
#include <cuda_runtime.h>
#include <cuda_bf16.h>

// Problem constants (shapes fixed by the dataset):
//   x:  (8, 64, 56, 56) fp32
//   lb: (64, 1, 1, 32) fp32   (tiled linspace left edges)
//   rb: (64, 1, 1, 32) fp32   (tiled linspace right edges)
//   out:(8, 32, 56, 56) fp32
#define NB   8
#define CI   64
#define CO   32
#define HW   3136              // 56*56
#define NPOS (NB * HW)         // 25088
#define PPB  64                // positions per block (3136 % 64 == 0)
#define NG   4                 // channel groups per block
#define CPG  (CI / NG)         // 16 channels per group
#define NT   (PPB * NG)        // 256 threads

__global__ __launch_bounds__(NT)
void local_basis_kernel(const float* __restrict__ x,
                        const float* __restrict__ lb,
                        const float* __restrict__ rb,
                        float* __restrict__ out)
{
    // One private accumulator copy per channel-group: breaks the smem
    // read-modify-write dependency chain into NG independent, shorter chains.
    // Layout acc[g][k*PPB + pos]: within a warp all lanes share g and have
    // consecutive pos -> one lane per bank, conflict-free for RMW, reduction
    // and init alike.
    __shared__ float acc[NG * CO * PPB];      // 4*32*64*4B = 32 KB

    const int pos = threadIdx.x;              // 0..63 (spatial position in block)
    const int g   = threadIdx.y;              // 0..3  (channel group)
    const int tid = g * PPB + pos;

    const int p = blockIdx.x * PPB + pos;     // linear (b,h,w) position
    const int b = p / HW;
    const int s = p - b * HW;

    // Bin geometry from the actual input arrays (uniform across channels/bins).
    const float lb0   = lb[0];
    const float w     = rb[0] - lb0;
    const float inv_w = 1.0f / w;
    const float norm  = 4.0f * inv_w * inv_w; // norm_const = 4/(rb-lb)^2

    // Zero all accumulator copies (vectorized: 8192 floats / 256 thr = 8 float4 each).
    float4* accv = reinterpret_cast<float4*>(acc);
    #pragma unroll
    for (int i = 0; i < (NG * CO * PPB / 4) / NT; i++)
        accv[tid + i * NT] = make_float4(0.f, 0.f, 0.f, 0.f);
    __syncthreads();

    // Main loop: each x lands in exactly one bin (bins are adjacent,
    // non-overlapping, width w < 1 so the +-1 clip is never active inside a
    // bin). Guards fmaxf(.,0) make any boundary case an exact 0, matching
    // the reference.
    const float* xp = x + (size_t)b * CI * HW + (size_t)g * CPG * HW + s;
    float* ag = &acc[g * CO * PPB + pos];

    #pragma unroll
    for (int c = 0; c < CPG; c++) {
        const float xv = xp[c * HW];
        const float t  = (xv - lb0) * inv_w;
        const int   k  = (int)t;
        if (t >= 0.0f && k < CO) {
            const float lbk = fmaf((float)k, w, lb0);
            const float d1r = xv - lbk;             // left  = x - lb_k
            const float d1  = fmaxf(d1r, 0.0f);
            const float d2  = fmaxf(w - d1r, 0.0f); // right = rb_k - x
            const float v   = d1 * d2 * norm;
            ag[k * PPB] = fmaf(v, v, ag[k * PPB]);
        }
        // x outside [lb0, lb0+CO*w): all bins give left*right <= 0 in the
        // reference too -> contribution is exactly 0; skipping is exact.
    }
    __syncthreads();

    // Reduce the NG partial copies and store. 2048 outputs / 256 threads = 8.
    // Lanes read/store consecutive addresses -> conflict-free smem reads,
    // 128B-coalesced global stores.
    #pragma unroll
    for (int i = 0; i < (CO * PPB) / NT; i++) {
        const int o = tid + i * NT;               // 0..2047
        float sum = 0.0f;
        #pragma unroll
        for (int gg = 0; gg < NG; gg++)
            sum += acc[gg * CO * PPB + o];
        const int k  = o >> 6;                    // o / PPB
        const int pp = o & (PPB - 1);             // o % PPB
        const int pg = blockIdx.x * PPB + pp;
        const int bb = pg / HW;
        const int ss = pg - bb * HW;
        out[(size_t)bb * CO * HW + (size_t)k * HW + ss] = sum;
    }
}

extern "C" void kernel_launch(void* const* d_in, const int* in_sizes, int n_in,
                              void* d_out, int out_size)
{
    const float* x  = (const float*)d_in[0];
    const float* lb = (const float*)d_in[1];
    const float* rb = (const float*)d_in[2];
    float* out      = (float*)d_out;

    dim3 block(PPB, NG);
    local_basis_kernel<<<NPOS / PPB, block>>>(x, lb, rb, out);
}